// round 2
// baseline (speedup 1.0000x reference)
#include <cuda_runtime.h>
#include <cuda_bf16.h>
#include <cstdint>

#define NMAX 50000
#define EMAX 800000
#define D 128

// ---------------- device scratch (static; no allocation allowed) ----------------
__device__ float g_xn[NMAX * D];        // layernormed x
__device__ float g_xw1[NMAX * 32];      // action layer1 projections, pre-scaled by dinv1 ([0:16)=in, [16:32)=out)
__device__ float g_acc1[NMAX * 32];     // scatter accumulator layer1
__device__ float g_t2[NMAX * 4];        // layer2 projections pre-scaled by dinv1 (in0,in1,out0,out1)
__device__ float g_acc2[NMAX * 4];      // scatter accumulator layer2
__device__ float g_dinv1[NMAX];
__device__ int   g_deg1[NMAX];
__device__ int   g_degm[NMAX];
__device__ float g_dinvm[NMAX];
__device__ unsigned char g_flags[NMAX]; // bit0 = in0, bit1 = out0
__device__ float g_xws[NMAX * D];       // (xn @ conv_w) * dinvm
__device__ int2  g_act[EMAX];           // compacted active edges (src,dst)
__device__ int   g_nact;

// vector reduction into global (sm_90+)
__device__ __forceinline__ void red4(float* p, float4 v) {
    asm volatile("red.global.add.v4.f32 [%0], {%1,%2,%3,%4};"
                 :: "l"(p), "f"(v.x), "f"(v.y), "f"(v.z), "f"(v.w) : "memory");
}

// ---------------- kernels ----------------

__global__ void k_init(int n) {
    int idx = blockIdx.x * blockDim.x + threadIdx.x;
    if (idx < n * 32) g_acc1[idx] = 0.f;
    if (idx < n * 4)  g_acc2[idx] = 0.f;
    if (idx < n)      { g_deg1[idx] = 0; g_degm[idx] = 0; }
    if (idx == 0)     g_nact = 0;
}

__global__ void k_deg1(const int* __restrict__ ei, int e_cnt) {
    int e = blockIdx.x * blockDim.x + threadIdx.x;
    if (e >= e_cnt) return;
    atomicAdd(&g_deg1[ei[e_cnt + e]], 1);
}

// LayerNorm + both action-net layer-1 projections (fused).
__global__ __launch_bounds__(256) void k_ln_proj(
    const float* __restrict__ x, const float* __restrict__ ln_g, const float* __restrict__ ln_b,
    const float* __restrict__ ia1_w, const float* __restrict__ oa1_w, int n)
{
    __shared__ float sW[D * 32];
    __shared__ float sxn[8][D];
    int tid = threadIdx.x;
    for (int i = tid; i < D * 32; i += 256) {
        int k = i >> 5, j = i & 31;
        sW[i] = (j < 16) ? ia1_w[k * 16 + j] : oa1_w[k * 16 + (j - 16)];
    }
    __syncthreads();
    int warp = tid >> 5, lane = tid & 31;
    int nwarps = gridDim.x * 8;
    for (int v = blockIdx.x * 8 + warp; v < n; v += nwarps) {
        float4 xv = ((const float4*)(x + (size_t)v * D))[lane];
        float s1 = xv.x + xv.y + xv.z + xv.w;
        float s2 = xv.x * xv.x + xv.y * xv.y + xv.z * xv.z + xv.w * xv.w;
        #pragma unroll
        for (int o = 16; o; o >>= 1) {
            s1 += __shfl_xor_sync(0xffffffffu, s1, o);
            s2 += __shfl_xor_sync(0xffffffffu, s2, o);
        }
        float mu = s1 * (1.f / 128.f);
        float var = s2 * (1.f / 128.f) - mu * mu;
        float rs = rsqrtf(var + 1e-5f);
        float4 g4 = ((const float4*)ln_g)[lane];
        float4 b4 = ((const float4*)ln_b)[lane];
        float4 o4;
        o4.x = (xv.x - mu) * rs * g4.x + b4.x;
        o4.y = (xv.y - mu) * rs * g4.y + b4.y;
        o4.z = (xv.z - mu) * rs * g4.z + b4.z;
        o4.w = (xv.w - mu) * rs * g4.w + b4.w;
        ((float4*)(g_xn + (size_t)v * D))[lane] = o4;
        ((float4*)sxn[warp])[lane] = o4;
        __syncwarp();
        float dinv = rsqrtf((float)g_deg1[v] + 1.0f);
        float acc = 0.f;
        const float* sx = sxn[warp];
        #pragma unroll 16
        for (int k = 0; k < D; k++) acc = fmaf(sx[k], sW[k * 32 + lane], acc);
        g_xw1[v * 32 + lane] = acc * dinv;
        if (lane == 0) g_dinv1[v] = dinv;
        __syncwarp();
    }
}

// scatter layer-1 messages: 8 float4 chunks per edge
__global__ void k_scatter1(const int* __restrict__ ei, int e_cnt) {
    int idx = blockIdx.x * blockDim.x + threadIdx.x;
    if (idx >= e_cnt * 8) return;
    int e = idx >> 3, c = idx & 7;
    int s = ei[e], d = ei[e_cnt + e];
    float4 v = *((const float4*)(g_xw1 + (size_t)s * 32) + c);
    red4(g_acc1 + (size_t)d * 32 + c * 4, v);
}

// finalize h (relu) + project to layer2 logits contribution (pre-scaled by dinv1)
__global__ void k_fin1(const float* __restrict__ ia1_b, const float* __restrict__ oa1_b,
                       const float* __restrict__ ia2_w, const float* __restrict__ oa2_w, int n)
{
    int tid = blockIdx.x * blockDim.x + threadIdx.x;
    int v = tid >> 5, lane = tid & 31;
    if (v >= n) return;
    float dinv = g_dinv1[v];
    float xw1s = g_xw1[v * 32 + lane];
    float bias = (lane < 16) ? ia1_b[lane] : oa1_b[lane - 16];
    float h = dinv * g_acc1[v * 32 + lane] + xw1s * dinv + bias;
    h = fmaxf(h, 0.f);
    float w0 = (lane < 16) ? ia2_w[lane * 2] : oa2_w[(lane - 16) * 2];
    float w1 = (lane < 16) ? ia2_w[lane * 2 + 1] : oa2_w[(lane - 16) * 2 + 1];
    float p0 = h * w0, p1 = h * w1;
    #pragma unroll
    for (int o = 8; o; o >>= 1) {
        p0 += __shfl_xor_sync(0xffffffffu, p0, o);
        p1 += __shfl_xor_sync(0xffffffffu, p1, o);
    }
    if (lane == 0)  { g_t2[v * 4 + 0] = p0 * dinv; g_t2[v * 4 + 1] = p1 * dinv; }
    if (lane == 16) { g_t2[v * 4 + 2] = p0 * dinv; g_t2[v * 4 + 3] = p1 * dinv; }
}

__global__ void k_scatter2(const int* __restrict__ ei, int e_cnt) {
    int e = blockIdx.x * blockDim.x + threadIdx.x;
    if (e >= e_cnt) return;
    int s = ei[e], d = ei[e_cnt + e];
    float4 t = *(const float4*)(g_t2 + (size_t)s * 4);
    red4(g_acc2 + (size_t)d * 4, t);
}

__global__ void k_gumbel(const float* __restrict__ u_in, const float* __restrict__ u_out,
                         const float* __restrict__ ia2_b, const float* __restrict__ oa2_b, int n)
{
    int v = blockIdx.x * blockDim.x + threadIdx.x;
    if (v >= n) return;
    float dinv = g_dinv1[v];
    float li0 = dinv * g_acc2[v * 4 + 0] + g_t2[v * 4 + 0] * dinv + ia2_b[0];
    float li1 = dinv * g_acc2[v * 4 + 1] + g_t2[v * 4 + 1] * dinv + ia2_b[1];
    float lo0 = dinv * g_acc2[v * 4 + 2] + g_t2[v * 4 + 2] * dinv + oa2_b[0];
    float lo1 = dinv * g_acc2[v * 4 + 3] + g_t2[v * 4 + 3] * dinv + oa2_b[1];
    float gi0 = -logf(-logf(u_in[v * 2 + 0] + 1e-10f) + 1e-10f);
    float gi1 = -logf(-logf(u_in[v * 2 + 1] + 1e-10f) + 1e-10f);
    float go0 = -logf(-logf(u_out[v * 2 + 0] + 1e-10f) + 1e-10f);
    float go1 = -logf(-logf(u_out[v * 2 + 1] + 1e-10f) + 1e-10f);
    int in0  = (li0 + gi0 >= li1 + gi1) ? 1 : 0;
    int out0 = (lo0 + go0 >= lo1 + go1) ? 1 : 0;
    g_flags[v] = (unsigned char)(in0 | (out0 << 1));
}

// weighted degree + warp-aggregated compaction of active edges
__global__ void k_compact(const int* __restrict__ ei, int e_cnt) {
    int e = blockIdx.x * blockDim.x + threadIdx.x;
    int lane = threadIdx.x & 31;
    int s = 0, d = 0, act = 0;
    if (e < e_cnt) {
        s = ei[e]; d = ei[e_cnt + e];
        act = (g_flags[d] & 1) && ((g_flags[s] >> 1) & 1);
    }
    unsigned m = __ballot_sync(0xffffffffu, act);
    if (m) {
        int leader = __ffs(m) - 1;
        int base = 0;
        if (lane == leader) base = atomicAdd(&g_nact, __popc(m));
        base = __shfl_sync(0xffffffffu, base, leader);
        if (act) {
            int r = __popc(m & ((1u << lane) - 1));
            g_act[base + r] = make_int2(s, d);
            atomicAdd(&g_degm[d], 1);
        }
    }
}

__global__ void k_dinvm(int n) {
    int v = blockIdx.x * blockDim.x + threadIdx.x;
    if (v < n) g_dinvm[v] = rsqrtf((float)g_degm[v] + 1.0f);
}

// xw = xn @ conv_w; store xws = xw*dinvm; init d_out = xws*dinvm + conv_b (self term + bias)
__global__ __launch_bounds__(256) void k_gemm(const float* __restrict__ conv_w,
                                              const float* __restrict__ conv_b,
                                              float* __restrict__ out, int n)
{
    __shared__ float sA[64][32];
    __shared__ float sB[32][D];
    int tid = threadIdx.x;
    int row0 = blockIdx.x * 64;
    int rb = (tid >> 5) * 8;
    int lane = tid & 31;
    int cb = lane * 4;
    float acc[8][4];
    #pragma unroll
    for (int r = 0; r < 8; r++) { acc[r][0]=0.f; acc[r][1]=0.f; acc[r][2]=0.f; acc[r][3]=0.f; }

    for (int kc = 0; kc < D; kc += 32) {
        for (int i = tid; i < 1024; i += 256) {             // sB: 32 x 128 floats = 1024 float4
            int r = i >> 5, c4 = i & 31;
            ((float4*)&sB[r][0])[c4] = ((const float4*)(conv_w + (size_t)(kc + r) * D))[c4];
        }
        for (int i = tid; i < 512; i += 256) {              // sA: 64 x 32 floats = 512 float4
            int r = i >> 3, c4 = i & 7;
            float4 vv = make_float4(0.f, 0.f, 0.f, 0.f);
            if (row0 + r < n)
                vv = ((const float4*)(g_xn + (size_t)(row0 + r) * D + kc))[c4];
            sA[r][c4 * 4 + 0] = vv.x; sA[r][c4 * 4 + 1] = vv.y;
            sA[r][c4 * 4 + 2] = vv.z; sA[r][c4 * 4 + 3] = vv.w;
        }
        __syncthreads();
        #pragma unroll
        for (int kk = 0; kk < 32; kk++) {
            float4 b = ((float4*)&sB[kk][0])[lane];
            float a[8];
            #pragma unroll
            for (int r = 0; r < 8; r++) a[r] = sA[rb + r][kk];
            #pragma unroll
            for (int r = 0; r < 8; r++) {
                acc[r][0] = fmaf(a[r], b.x, acc[r][0]);
                acc[r][1] = fmaf(a[r], b.y, acc[r][1]);
                acc[r][2] = fmaf(a[r], b.z, acc[r][2]);
                acc[r][3] = fmaf(a[r], b.w, acc[r][3]);
            }
        }
        __syncthreads();
    }
    float4 bb = ((const float4*)conv_b)[lane];
    #pragma unroll
    for (int r = 0; r < 8; r++) {
        int v = row0 + rb + r;
        if (v < n) {
            float dm = g_dinvm[v];
            float4 w = make_float4(acc[r][0]*dm, acc[r][1]*dm, acc[r][2]*dm, acc[r][3]*dm);
            ((float4*)(g_xws + (size_t)v * D))[lane] = w;
            float4 o = make_float4(w.x*dm + bb.x, w.y*dm + bb.y, w.z*dm + bb.z, w.w*dm + bb.w);
            ((float4*)(out + (size_t)v * D))[lane] = o;
        }
    }
}

// main conv scatter over compacted active edges (one warp per edge, grid-stride)
__global__ void k_scatter_main(float* __restrict__ out) {
    int gw = (blockIdx.x * blockDim.x + threadIdx.x) >> 5;
    int lane = threadIdx.x & 31;
    int nw = (gridDim.x * blockDim.x) >> 5;
    int nact = g_nact;
    for (int e = gw; e < nact; e += nw) {
        int2 sd = g_act[e];
        float dm = g_dinvm[sd.y];
        float4 v = ((const float4*)(g_xws + (size_t)sd.x * D))[lane];
        v.x *= dm; v.y *= dm; v.z *= dm; v.w *= dm;
        red4(out + (size_t)sd.y * D + lane * 4, v);
    }
}

// edge_features = relu(edge_attr @ ep_w + ep_b), scattered into out (one warp per edge)
__global__ __launch_bounds__(256) void k_edgefeat(const int* __restrict__ ei,
                                                  const float* __restrict__ ea,
                                                  const float* __restrict__ ep_w,
                                                  const float* __restrict__ ep_b,
                                                  float* __restrict__ out, int e_cnt)
{
    __shared__ float sW[16 * D];
    int tid = threadIdx.x;
    for (int i = tid; i < 512; i += 256)
        ((float4*)sW)[i] = ((const float4*)ep_w)[i];
    __syncthreads();
    int e = blockIdx.x * 8 + (tid >> 5);
    if (e >= e_cnt) return;
    int lane = tid & 31;
    int d = ei[e_cnt + e];
    const float4* ea4 = (const float4*)(ea + (size_t)e * 16);
    float4 a0 = ea4[0], a1 = ea4[1], a2 = ea4[2], a3 = ea4[3];
    float4 acc = ((const float4*)ep_b)[lane];
    const float ak[16] = {a0.x,a0.y,a0.z,a0.w, a1.x,a1.y,a1.z,a1.w,
                          a2.x,a2.y,a2.z,a2.w, a3.x,a3.y,a3.z,a3.w};
    #pragma unroll
    for (int k = 0; k < 16; k++) {
        float4 w = ((const float4*)(sW + k * D))[lane];
        acc.x = fmaf(ak[k], w.x, acc.x);
        acc.y = fmaf(ak[k], w.y, acc.y);
        acc.z = fmaf(ak[k], w.z, acc.z);
        acc.w = fmaf(ak[k], w.w, acc.w);
    }
    acc.x = fmaxf(acc.x, 0.f); acc.y = fmaxf(acc.y, 0.f);
    acc.z = fmaxf(acc.z, 0.f); acc.w = fmaxf(acc.w, 0.f);
    red4(out + (size_t)d * D + lane * 4, acc);
}

__global__ void k_relu(float* __restrict__ out, int n4) {
    int i = blockIdx.x * blockDim.x + threadIdx.x;
    if (i >= n4) return;
    float4 v = ((float4*)out)[i];
    v.x = fmaxf(v.x, 0.f); v.y = fmaxf(v.y, 0.f);
    v.z = fmaxf(v.z, 0.f); v.w = fmaxf(v.w, 0.f);
    ((float4*)out)[i] = v;
}

// ---------------- launch ----------------
extern "C" void kernel_launch(void* const* d_in, const int* in_sizes, int n_in,
                              void* d_out, int out_size)
{
    const float* x      = (const float*)d_in[0];
    const int*   ei     = (const int*)  d_in[1];
    const float* ea     = (const float*)d_in[2];
    const float* u_in   = (const float*)d_in[3];
    const float* u_out  = (const float*)d_in[4];
    const float* ln_g   = (const float*)d_in[5];
    const float* ln_b   = (const float*)d_in[6];
    const float* conv_w = (const float*)d_in[7];
    const float* conv_b = (const float*)d_in[8];
    const float* ep_w   = (const float*)d_in[9];
    const float* ep_b   = (const float*)d_in[10];
    const float* ia1_w  = (const float*)d_in[11];
    const float* ia1_b  = (const float*)d_in[12];
    const float* ia2_w  = (const float*)d_in[13];
    const float* ia2_b  = (const float*)d_in[14];
    const float* oa1_w  = (const float*)d_in[15];
    const float* oa1_b  = (const float*)d_in[16];
    const float* oa2_w  = (const float*)d_in[17];
    const float* oa2_b  = (const float*)d_in[18];

    int n = in_sizes[0] / D;       // 50000
    int e = in_sizes[1] / 2;       // 800000
    float* out = (float*)d_out;

    k_init<<<(n * 32 + 255) / 256, 256>>>(n);
    k_deg1<<<(e + 255) / 256, 256>>>(ei, e);
    k_ln_proj<<<592, 256>>>(x, ln_g, ln_b, ia1_w, oa1_w, n);
    k_scatter1<<<(e * 8 + 255) / 256, 256>>>(ei, e);
    k_fin1<<<(n * 32 + 255) / 256, 256>>>(ia1_b, oa1_b, ia2_w, oa2_w, n);
    k_scatter2<<<(e + 255) / 256, 256>>>(ei, e);
    k_gumbel<<<(n + 255) / 256, 256>>>(u_in, u_out, ia2_b, oa2_b, n);
    k_compact<<<(e + 255) / 256, 256>>>(ei, e);
    k_dinvm<<<(n + 255) / 256, 256>>>(n);
    k_gemm<<<(n + 63) / 64, 256>>>(conv_w, conv_b, out, n);
    k_scatter_main<<<1184, 256>>>(out);
    k_edgefeat<<<(e + 7) / 8, 256>>>(ei, ea, ep_w, ep_b, out, e);
    k_relu<<<(n * 32 + 255) / 256, 256>>>(out, n * 32);
}